// round 2
// baseline (speedup 1.0000x reference)
#include <cuda_runtime.h>
#include <math.h>

#define PAD 68
#define SMEM_FLOATS (3*64*PAD + 128)
#define SMEM_BYTES  (SMEM_FLOATS * 4)

// column-softmaxed weights, o-major: g_wT[o*64 + i] = w[i][o]
__device__ float g_wT[64 * 64];

__global__ void wprep_kernel(const float* __restrict__ wraw) {
    int o = threadIdx.x;  // 64 threads, one output column each
    float s = 0.f;
    #pragma unroll 8
    for (int i = 0; i < 64; ++i) s += expf(wraw[i * 64 + o]);
    float inv = 1.0f / s;
    #pragma unroll 8
    for (int i = 0; i < 64; ++i) g_wT[o * 64 + i] = expf(wraw[i * 64 + o]) * inv;
}

__global__ __launch_bounds__(128, 4) void mfd_kernel(const float* __restrict__ xg,
                                                     float* __restrict__ out) {
    extern __shared__ float sm[];
    float* Xs  = sm;                 // [64][PAD]  x rows
    float* As  = Xs + 64 * PAD;      // [64][PAD]  current iterate a
    float* Fs  = As + 64 * PAD;      // [64][PAD]  F matrix
    float* Sxx = Fs + 64 * PAD;      // [64]  ||x_i||^2
    float* Saa = Sxx + 64;           // [64]  ||a_o||^2

    const int n   = blockIdx.x;
    const int tid = threadIdx.x;
    const int oc  = tid >> 4;        // 0..7
    const int ic  = tid & 15;        // 0..15

    // ---- load x tile (coalesced float4) ----
    const float* xn = xg + (size_t)n * 4096;
    for (int t = tid; t < 1024; t += 128) {
        float4 v = ((const float4*)xn)[t];
        int r = t >> 4, c = (t & 15) << 2;
        *(float4*)&Xs[r * PAD + c] = v;
    }
    __syncthreads();

    // ---- per-row squared norms of x ----
    if (tid < 64) {
        float s = 0.f;
        #pragma unroll
        for (int c = 0; c < 64; c += 4) {
            float4 v = *(float4*)&Xs[tid * PAD + c];
            s += v.x * v.x + v.y * v.y + v.z * v.z + v.w * v.w;
        }
        Sxx[tid] = s;
    }
    __syncthreads();

    // ---- init a_o = x_0 for all o ----
    for (int t = tid; t < 1024; t += 128) {
        int r = t >> 4, c = (t & 15) << 2;
        *(float4*)&As[r * PAD + c] = *(float4*)&Xs[c];
    }
    if (tid < 64) Saa[tid] = Sxx[0];
    __syncthreads();

    const float HI = 1.0f - 1e-7f;

    for (int it = 0; it < 3; ++it) {
        // ===== GEMM1: D[o][i] = sum_dd A[o][dd] * X[i][dd] =====
        float acc[8][4];
        #pragma unroll
        for (int k = 0; k < 8; ++k)
            #pragma unroll
            for (int j = 0; j < 4; ++j) acc[k][j] = 0.f;

        #pragma unroll 4
        for (int dd = 0; dd < 64; dd += 4) {
            float4 xv[4];
            #pragma unroll
            for (int j = 0; j < 4; ++j)
                xv[j] = *(float4*)&Xs[(ic + 16 * j) * PAD + dd];
            #pragma unroll
            for (int k = 0; k < 8; ++k) {
                float4 av = *(float4*)&As[(oc + 8 * k) * PAD + dd];
                #pragma unroll
                for (int j = 0; j < 4; ++j) {
                    acc[k][j] = fmaf(av.x, xv[j].x, acc[k][j]);
                    acc[k][j] = fmaf(av.y, xv[j].y, acc[k][j]);
                    acc[k][j] = fmaf(av.z, xv[j].z, acc[k][j]);
                    acc[k][j] = fmaf(av.w, xv[j].w, acc[k][j]);
                }
            }
        }

        // ===== build F[o][i] = w[i][o] * theta / ||v||, accumulate corr =====
        float corr[8];
        #pragma unroll
        for (int k = 0; k < 8; ++k) {
            int o = oc + 8 * k;
            float sa = Saa[o];
            float cr = 0.f;
            #pragma unroll
            for (int j = 0; j < 4; ++j) {
                int i = ic + 16 * j;
                float draw  = acc[k][j];
                float dc    = fminf(fmaxf(draw, -HI), HI);
                float theta = acosf(dc);
                float nv2   = Sxx[i] - dc * (2.0f * draw - dc * sa);
                float f     = (nv2 < 1e-14f) ? 1.0f : theta * rsqrtf(nv2);
                float F     = g_wT[o * 64 + i] * f;
                Fs[o * PAD + i] = F;
                cr = fmaf(F, dc, cr);
            }
            corr[k] = cr;
        }
        // reduce corr over the 16 lanes sharing this o-group
        #pragma unroll
        for (int k = 0; k < 8; ++k) {
            #pragma unroll
            for (int s = 1; s < 16; s <<= 1)
                corr[k] += __shfl_xor_sync(0xffffffffu, corr[k], s);
        }
        __syncthreads();  // Fs complete

        // ===== GEMM2: G[o][dd] = sum_i F[o][i] * X[i][dd] =====
        float g[8][4];
        #pragma unroll
        for (int k = 0; k < 8; ++k)
            #pragma unroll
            for (int j = 0; j < 4; ++j) g[k][j] = 0.f;

        #pragma unroll 4
        for (int i4 = 0; i4 < 64; i4 += 4) {
            float xc0[4], xc1[4], xc2[4], xc3[4];
            #pragma unroll
            for (int j = 0; j < 4; ++j) {
                int dd = ic + 16 * j;
                xc0[j] = Xs[(i4 + 0) * PAD + dd];
                xc1[j] = Xs[(i4 + 1) * PAD + dd];
                xc2[j] = Xs[(i4 + 2) * PAD + dd];
                xc3[j] = Xs[(i4 + 3) * PAD + dd];
            }
            #pragma unroll
            for (int k = 0; k < 8; ++k) {
                float4 fv = *(float4*)&Fs[(oc + 8 * k) * PAD + i4];
                #pragma unroll
                for (int j = 0; j < 4; ++j) {
                    g[k][j] = fmaf(fv.x, xc0[j], g[k][j]);
                    g[k][j] = fmaf(fv.y, xc1[j], g[k][j]);
                    g[k][j] = fmaf(fv.z, xc2[j], g[k][j]);
                    g[k][j] = fmaf(fv.w, xc3[j], g[k][j]);
                }
            }
        }

        // ===== exp-map update =====
        #pragma unroll
        for (int k = 0; k < 8; ++k) {
            int o = oc + 8 * k;
            float aold[4], grad[4];
            float gn2 = 0.f;
            #pragma unroll
            for (int j = 0; j < 4; ++j) {
                int dd = ic + 16 * j;
                aold[j] = As[o * PAD + dd];
                grad[j] = g[k][j] - corr[k] * aold[j];
                gn2 = fmaf(grad[j], grad[j], gn2);
            }
            #pragma unroll
            for (int s = 1; s < 16; s <<= 1)
                gn2 += __shfl_xor_sync(0xffffffffu, gn2, s);
            float gn = sqrtf(gn2);
            float sg, cg;
            sincosf(gn, &sg, &cg);
            float sc = (gn < 1e-7f) ? 1.0f : sg / gn;

            if (it == 2) {
                #pragma unroll
                for (int j = 0; j < 4; ++j) {
                    int dd = ic + 16 * j;
                    out[(size_t)n * 4096 + o * 64 + dd] = fmaf(cg, aold[j], sc * grad[j]);
                }
            } else {
                float sa2 = 0.f;
                #pragma unroll
                for (int j = 0; j < 4; ++j) {
                    int dd = ic + 16 * j;
                    float an = fmaf(cg, aold[j], sc * grad[j]);
                    As[o * PAD + dd] = an;
                    sa2 = fmaf(an, an, sa2);
                }
                #pragma unroll
                for (int s = 1; s < 16; s <<= 1)
                    sa2 += __shfl_xor_sync(0xffffffffu, sa2, s);
                if (ic == 0) Saa[o] = sa2;
            }
        }
        __syncthreads();  // As/Saa ready for next iteration
    }
}

extern "C" void kernel_launch(void* const* d_in, const int* in_sizes, int n_in,
                              void* d_out, int out_size) {
    const float* x    = (const float*)d_in[0];   // (4,256,64,64)
    const float* wraw = (const float*)d_in[1];   // (64,64)
    float* out = (float*)d_out;                  // (4,256,64,64)

    cudaFuncSetAttribute(mfd_kernel, cudaFuncAttributeMaxDynamicSharedMemorySize, SMEM_BYTES);

    wprep_kernel<<<1, 64>>>(wraw);
    mfd_kernel<<<1024, 128, SMEM_BYTES>>>(x, out);
}

// round 3
// speedup vs baseline: 1.0035x; 1.0035x over previous
#include <cuda_runtime.h>
#include <math.h>

#define PAD 68
#define ARR (64 * PAD)
#define SMEM_FLOATS (4 * ARR + 128)
#define SMEM_BYTES (SMEM_FLOATS * 4)

typedef unsigned long long u64;

// column-softmaxed weights, o-major: g_wT[o*64 + i] = w[i][o]
__device__ float g_wT[64 * 64];

static __device__ __forceinline__ u64 ffma2(u64 a, u64 b, u64 c) {
    u64 d; asm("fma.rn.f32x2 %0,%1,%2,%3;" : "=l"(d) : "l"(a), "l"(b), "l"(c)); return d;
}
static __device__ __forceinline__ float hadd2(u64 v) {
    float lo, hi; asm("mov.b64 {%0,%1},%2;" : "=f"(lo), "=f"(hi) : "l"(v));
    return lo + hi;
}

__global__ void wprep_kernel(const float* __restrict__ wraw) {
    int o = threadIdx.x;  // 64 threads, one output column each
    float s = 0.f;
    #pragma unroll 8
    for (int i = 0; i < 64; ++i) s += expf(wraw[i * 64 + o]);
    float inv = 1.0f / s;
    #pragma unroll 8
    for (int i = 0; i < 64; ++i) g_wT[o * 64 + i] = expf(wraw[i * 64 + o]) * inv;
}

__global__ __launch_bounds__(128, 3) void mfd_kernel(const float* __restrict__ xg,
                                                     float* __restrict__ out) {
    extern __shared__ float sm[];
    float* Xs  = sm;              // [64][PAD]  x rows (dd-contiguous)
    float* XT  = Xs + ARR;        // [64][PAD]  x transposed (i-contiguous per dd-row)
    float* As  = XT + ARR;        // [64][PAD]  current iterate a
    float* Fs  = As + ARR;        // [64][PAD]  F matrix (i-contiguous per o-row)
    float* Sxx = Fs + ARR;        // [64]  ||x_i||^2
    float* Saa = Sxx + 64;        // [64]  ||a_o||^2

    const int n   = blockIdx.x;
    const int tid = threadIdx.x;
    const int oc  = tid >> 4;     // 0..7
    const int ic  = tid & 15;     // 0..15

    // ---- load x tile (coalesced float4) ----
    const float* xn = xg + (size_t)n * 4096;
    for (int t = tid; t < 1024; t += 128) {
        float4 v = ((const float4*)xn)[t];
        int r = t >> 4, c = (t & 15) << 2;
        *(float4*)&Xs[r * PAD + c] = v;
    }
    __syncthreads();

    // ---- transpose into XT, and per-row squared norms of x ----
    for (int t = tid; t < 1024; t += 128) {
        int dd = t >> 4, i0 = (t & 15) << 2;
        float4 v;
        v.x = Xs[(i0 + 0) * PAD + dd];
        v.y = Xs[(i0 + 1) * PAD + dd];
        v.z = Xs[(i0 + 2) * PAD + dd];
        v.w = Xs[(i0 + 3) * PAD + dd];
        *(float4*)&XT[dd * PAD + i0] = v;
    }
    if (tid < 64) {
        float s = 0.f;
        #pragma unroll
        for (int c = 0; c < 64; c += 4) {
            float4 v = *(float4*)&Xs[tid * PAD + c];
            s += v.x * v.x + v.y * v.y + v.z * v.z + v.w * v.w;
        }
        Sxx[tid] = s;
    }
    // ---- init a_o = x_0 for all o ----
    for (int t = tid; t < 1024; t += 128) {
        int r = t >> 4, c = (t & 15) << 2;
        *(float4*)&As[r * PAD + c] = *(float4*)&Xs[c];
    }
    __syncthreads();
    if (tid < 64) Saa[tid] = Sxx[0];
    __syncthreads();

    const float HI = 1.0f - 1e-7f;

    #pragma unroll 1
    for (int it = 0; it < 3; ++it) {
        // ===== GEMM1 (f32x2, packed along dd): D[o][i] = sum_dd A[o][dd]*X[i][dd]
        u64 acc2[8][4];
        #pragma unroll
        for (int k = 0; k < 8; ++k)
            #pragma unroll
            for (int j = 0; j < 4; ++j) acc2[k][j] = 0ull;

        #pragma unroll 4
        for (int dd = 0; dd < 64; dd += 4) {
            ulonglong2 xp[4];
            #pragma unroll
            for (int j = 0; j < 4; ++j)
                xp[j] = *(const ulonglong2*)&Xs[(ic + 16 * j) * PAD + dd];
            #pragma unroll
            for (int k = 0; k < 8; ++k) {
                ulonglong2 ap = *(const ulonglong2*)&As[(oc + 8 * k) * PAD + dd];
                #pragma unroll
                for (int j = 0; j < 4; ++j) {
                    acc2[k][j] = ffma2(ap.x, xp[j].x, acc2[k][j]);
                    acc2[k][j] = ffma2(ap.y, xp[j].y, acc2[k][j]);
                }
            }
        }

        // ===== F[o][i] = w[i][o] * theta / ||v||, plus corr = sum_i F*dc
        float corr[8];
        #pragma unroll
        for (int k = 0; k < 8; ++k) {
            int o = oc + 8 * k;
            float sa = Saa[o];
            float cr = 0.f;
            #pragma unroll
            for (int j = 0; j < 4; ++j) {
                int i = ic + 16 * j;
                float draw  = hadd2(acc2[k][j]);
                float dc    = fminf(fmaxf(draw, -HI), HI);
                float theta = acosf(dc);
                float nv2   = Sxx[i] - dc * (2.0f * draw - dc * sa);
                float f     = (nv2 < 1e-14f) ? 1.0f : theta * rsqrtf(nv2);
                float F     = g_wT[o * 64 + i] * f;
                Fs[o * PAD + i] = F;
                cr = fmaf(F, dc, cr);
            }
            corr[k] = cr;
        }
        #pragma unroll
        for (int k = 0; k < 8; ++k) {
            #pragma unroll
            for (int s = 1; s < 16; s <<= 1)
                corr[k] += __shfl_xor_sync(0xffffffffu, corr[k], s);
        }
        __syncthreads();  // Fs complete

        // ===== GEMM2 (f32x2, packed along i): G[o][dd] = sum_i F[o][i]*XT[dd][i]
        u64 g2[8][4];
        #pragma unroll
        for (int k = 0; k < 8; ++k)
            #pragma unroll
            for (int j = 0; j < 4; ++j) g2[k][j] = 0ull;

        #pragma unroll 4
        for (int i4 = 0; i4 < 64; i4 += 4) {
            ulonglong2 xtp[4];
            #pragma unroll
            for (int j = 0; j < 4; ++j)
                xtp[j] = *(const ulonglong2*)&XT[(ic + 16 * j) * PAD + i4];
            #pragma unroll
            for (int k = 0; k < 8; ++k) {
                ulonglong2 fp = *(const ulonglong2*)&Fs[(oc + 8 * k) * PAD + i4];
                #pragma unroll
                for (int j = 0; j < 4; ++j) {
                    g2[k][j] = ffma2(fp.x, xtp[j].x, g2[k][j]);
                    g2[k][j] = ffma2(fp.y, xtp[j].y, g2[k][j]);
                }
            }
        }

        // ===== exp-map update =====
        #pragma unroll
        for (int k = 0; k < 8; ++k) {
            int o = oc + 8 * k;
            float aold[4], grad[4];
            float gn2 = 0.f;
            #pragma unroll
            for (int j = 0; j < 4; ++j) {
                int dd = ic + 16 * j;
                aold[j] = As[o * PAD + dd];
                grad[j] = hadd2(g2[k][j]) - corr[k] * aold[j];
                gn2 = fmaf(grad[j], grad[j], gn2);
            }
            #pragma unroll
            for (int s = 1; s < 16; s <<= 1)
                gn2 += __shfl_xor_sync(0xffffffffu, gn2, s);
            float gn = sqrtf(gn2);
            float sg, cg;
            sincosf(gn, &sg, &cg);
            float sc = (gn < 1e-7f) ? 1.0f : sg / gn;

            if (it == 2) {
                #pragma unroll
                for (int j = 0; j < 4; ++j) {
                    int dd = ic + 16 * j;
                    out[(size_t)n * 4096 + o * 64 + dd] = fmaf(cg, aold[j], sc * grad[j]);
                }
            } else {
                float sa2 = 0.f;
                #pragma unroll
                for (int j = 0; j < 4; ++j) {
                    int dd = ic + 16 * j;
                    float an = fmaf(cg, aold[j], sc * grad[j]);
                    As[o * PAD + dd] = an;
                    sa2 = fmaf(an, an, sa2);
                }
                #pragma unroll
                for (int s = 1; s < 16; s <<= 1)
                    sa2 += __shfl_xor_sync(0xffffffffu, sa2, s);
                if (ic == 0) Saa[o] = sa2;
            }
        }
        __syncthreads();  // As/Saa ready for next iteration
    }
}

extern "C" void kernel_launch(void* const* d_in, const int* in_sizes, int n_in,
                              void* d_out, int out_size) {
    const float* x    = (const float*)d_in[0];   // (4,256,64,64)
    const float* wraw = (const float*)d_in[1];   // (64,64)
    float* out = (float*)d_out;                  // (4,256,64,64)

    cudaFuncSetAttribute(mfd_kernel, cudaFuncAttributeMaxDynamicSharedMemorySize, SMEM_BYTES);

    wprep_kernel<<<1, 64>>>(wraw);
    mfd_kernel<<<1024, 128, SMEM_BYTES>>>(x, out);
}

// round 4
// speedup vs baseline: 1.1676x; 1.1635x over previous
#include <cuda_runtime.h>
#include <math.h>

#define PAD 68
#define ARR (64 * PAD)
#define SMEM_FLOATS (4 * ARR + 128)
#define SMEM_BYTES (SMEM_FLOATS * 4)

typedef unsigned long long u64;

// column-softmaxed weights, o-major: g_wT[o*64 + i] = w[i][o]
__device__ float g_wT[64 * 64];

static __device__ __forceinline__ u64 ffma2(u64 a, u64 b, u64 c) {
    u64 d; asm("fma.rn.f32x2 %0,%1,%2,%3;" : "=l"(d) : "l"(a), "l"(b), "l"(c)); return d;
}
static __device__ __forceinline__ float hadd2(u64 v) {
    float lo, hi; asm("mov.b64 {%0,%1},%2;" : "=f"(lo), "=f"(hi) : "l"(v));
    return lo + hi;
}

// acos via A&S 4.4.45 7-term poly: abs err ~2e-8 on [-1,1]
static __device__ __forceinline__ float acos_fast(float x) {
    float ax = fabsf(x);
    float p = fmaf(ax, -0.0012624911f, 0.0066700901f);
    p = fmaf(p, ax, -0.0170881256f);
    p = fmaf(p, ax, 0.0308918810f);
    p = fmaf(p, ax, -0.0501743046f);
    p = fmaf(p, ax, 0.0889789874f);
    p = fmaf(p, ax, -0.2145988016f);
    p = fmaf(p, ax, 1.5707963050f);
    float om = 1.0f - ax;                       // >= 1e-7 after clipping
    float s = om * rsqrtf(fmaxf(om, 1e-30f));   // sqrt(1-ax)
    float r = p * s;
    return (x < 0.0f) ? 3.14159265358979f - r : r;
}

__global__ void wprep_kernel(const float* __restrict__ wraw) {
    int o = threadIdx.x;  // 64 threads, one output column each
    float s = 0.f;
    #pragma unroll 8
    for (int i = 0; i < 64; ++i) s += expf(wraw[i * 64 + o]);
    float inv = 1.0f / s;
    #pragma unroll 8
    for (int i = 0; i < 64; ++i) g_wT[o * 64 + i] = expf(wraw[i * 64 + o]) * inv;
}

__global__ __launch_bounds__(256, 3) void mfd_kernel(const float* __restrict__ xg,
                                                     float* __restrict__ out) {
    extern __shared__ float sm[];
    float* Xs  = sm;              // [64][PAD]  x rows (dd-contiguous)
    float* XT  = Xs + ARR;        // [64][PAD]  x transposed (i-contiguous per dd-row)
    float* As  = XT + ARR;        // [64][PAD]  current iterate a
    float* Fs  = As + ARR;        // [64][PAD]  F matrix (i-contiguous per o-row)
    float* Sxx = Fs + ARR;        // [64]  ||x_i||^2
    float* Saa = Sxx + 64;        // [64]  ||a_o||^2

    const int n   = blockIdx.x;
    const int tid = threadIdx.x;
    const int oc  = tid >> 4;     // 0..15
    const int ic  = tid & 15;     // 0..15

    // ---- load x tile (coalesced float4) ----
    const float* xn = xg + (size_t)n * 4096;
    for (int t = tid; t < 1024; t += 256) {
        float4 v = ((const float4*)xn)[t];
        int r = t >> 4, c = (t & 15) << 2;
        *(float4*)&Xs[r * PAD + c] = v;
    }
    __syncthreads();

    // ---- transpose into XT, and per-row squared norms of x ----
    for (int t = tid; t < 1024; t += 256) {
        int dd = t >> 4, i0 = (t & 15) << 2;
        float4 v;
        v.x = Xs[(i0 + 0) * PAD + dd];
        v.y = Xs[(i0 + 1) * PAD + dd];
        v.z = Xs[(i0 + 2) * PAD + dd];
        v.w = Xs[(i0 + 3) * PAD + dd];
        *(float4*)&XT[dd * PAD + i0] = v;
    }
    if (tid < 64) {
        float s = 0.f;
        #pragma unroll
        for (int c = 0; c < 64; c += 4) {
            float4 v = *(float4*)&Xs[tid * PAD + c];
            s += v.x * v.x + v.y * v.y + v.z * v.z + v.w * v.w;
        }
        Sxx[tid] = s;
    }
    // ---- init a_o = x_0 for all o ----
    for (int t = tid; t < 1024; t += 256) {
        int r = t >> 4, c = (t & 15) << 2;
        *(float4*)&As[r * PAD + c] = *(float4*)&Xs[c];
    }
    __syncthreads();
    if (tid < 64) Saa[tid] = Sxx[0];
    __syncthreads();

    const float HI = 1.0f - 1e-7f;

    #pragma unroll 1
    for (int it = 0; it < 3; ++it) {
        // ===== GEMM1 (f32x2 along dd): D[o][i] = sum_dd A[o][dd]*X[i][dd]
        u64 acc2[4][4];
        #pragma unroll
        for (int k = 0; k < 4; ++k)
            #pragma unroll
            for (int j = 0; j < 4; ++j) acc2[k][j] = 0ull;

        #pragma unroll 4
        for (int dd = 0; dd < 64; dd += 4) {
            ulonglong2 xp[4];
            #pragma unroll
            for (int j = 0; j < 4; ++j)
                xp[j] = *(const ulonglong2*)&Xs[(ic + 16 * j) * PAD + dd];
            #pragma unroll
            for (int k = 0; k < 4; ++k) {
                ulonglong2 ap = *(const ulonglong2*)&As[(oc + 16 * k) * PAD + dd];
                #pragma unroll
                for (int j = 0; j < 4; ++j) {
                    acc2[k][j] = ffma2(ap.x, xp[j].x, acc2[k][j]);
                    acc2[k][j] = ffma2(ap.y, xp[j].y, acc2[k][j]);
                }
            }
        }

        // ===== F[o][i] = w[i][o] * theta / ||v||, plus corr = sum_i F*dc
        float corr[4];
        #pragma unroll
        for (int k = 0; k < 4; ++k) {
            int o = oc + 16 * k;
            float sa = Saa[o];
            float cr = 0.f;
            #pragma unroll
            for (int j = 0; j < 4; ++j) {
                int i = ic + 16 * j;
                float draw  = hadd2(acc2[k][j]);
                float dc    = fminf(fmaxf(draw, -HI), HI);
                float theta = acos_fast(dc);
                float nv2   = Sxx[i] - dc * (2.0f * draw - dc * sa);
                float f     = (nv2 < 1e-14f) ? 1.0f : theta * rsqrtf(nv2);
                float F     = g_wT[o * 64 + i] * f;
                Fs[o * PAD + i] = F;
                cr = fmaf(F, dc, cr);
            }
            corr[k] = cr;
        }
        #pragma unroll
        for (int k = 0; k < 4; ++k) {
            #pragma unroll
            for (int s = 1; s < 16; s <<= 1)
                corr[k] += __shfl_xor_sync(0xffffffffu, corr[k], s);
        }
        __syncthreads();  // Fs complete

        // ===== GEMM2 (f32x2 along i): G[o][dd] = sum_i F[o][i]*XT[dd][i]
        u64 g2[4][4];
        #pragma unroll
        for (int k = 0; k < 4; ++k)
            #pragma unroll
            for (int j = 0; j < 4; ++j) g2[k][j] = 0ull;

        #pragma unroll 4
        for (int i4 = 0; i4 < 64; i4 += 4) {
            ulonglong2 xtp[4];
            #pragma unroll
            for (int j = 0; j < 4; ++j)
                xtp[j] = *(const ulonglong2*)&XT[(ic + 16 * j) * PAD + i4];
            #pragma unroll
            for (int k = 0; k < 4; ++k) {
                ulonglong2 fp = *(const ulonglong2*)&Fs[(oc + 16 * k) * PAD + i4];
                #pragma unroll
                for (int j = 0; j < 4; ++j) {
                    g2[k][j] = ffma2(fp.x, xtp[j].x, g2[k][j]);
                    g2[k][j] = ffma2(fp.y, xtp[j].y, g2[k][j]);
                }
            }
        }

        // ===== exp-map update =====
        #pragma unroll
        for (int k = 0; k < 4; ++k) {
            int o = oc + 16 * k;
            float aold[4], grad[4];
            float gn2 = 0.f;
            #pragma unroll
            for (int j = 0; j < 4; ++j) {
                int dd = ic + 16 * j;
                aold[j] = As[o * PAD + dd];
                grad[j] = hadd2(g2[k][j]) - corr[k] * aold[j];
                gn2 = fmaf(grad[j], grad[j], gn2);
            }
            #pragma unroll
            for (int s = 1; s < 16; s <<= 1)
                gn2 += __shfl_xor_sync(0xffffffffu, gn2, s);
            float inv = rsqrtf(fmaxf(gn2, 1e-30f));
            float gn = gn2 * inv;                 // sqrt(gn2)
            float sg, cg;
            __sincosf(gn, &sg, &cg);
            float sc = (gn2 < 1e-14f) ? 1.0f : sg * inv;
            if (gn2 < 1e-14f) cg = 1.0f;

            if (it == 2) {
                #pragma unroll
                for (int j = 0; j < 4; ++j) {
                    int dd = ic + 16 * j;
                    out[(size_t)n * 4096 + o * 64 + dd] = fmaf(cg, aold[j], sc * grad[j]);
                }
            } else {
                float sa2 = 0.f;
                #pragma unroll
                for (int j = 0; j < 4; ++j) {
                    int dd = ic + 16 * j;
                    float an = fmaf(cg, aold[j], sc * grad[j]);
                    As[o * PAD + dd] = an;
                    sa2 = fmaf(an, an, sa2);
                }
                #pragma unroll
                for (int s = 1; s < 16; s <<= 1)
                    sa2 += __shfl_xor_sync(0xffffffffu, sa2, s);
                if (ic == 0) Saa[o] = sa2;
            }
        }
        __syncthreads();  // As/Saa ready for next iteration
    }
}

extern "C" void kernel_launch(void* const* d_in, const int* in_sizes, int n_in,
                              void* d_out, int out_size) {
    const float* x    = (const float*)d_in[0];   // (4,256,64,64)
    const float* wraw = (const float*)d_in[1];   // (64,64)
    float* out = (float*)d_out;                  // (4,256,64,64)

    cudaFuncSetAttribute(mfd_kernel, cudaFuncAttributeMaxDynamicSharedMemorySize, SMEM_BYTES);

    wprep_kernel<<<1, 64>>>(wraw);
    mfd_kernel<<<1024, 256, SMEM_BYTES>>>(x, out);
}

// round 5
// speedup vs baseline: 1.1874x; 1.0170x over previous
#include <cuda_runtime.h>
#include <math.h>

#define PAD 68
#define ARR (64 * PAD)
#define SMEM_FLOATS (4 * ARR + 128)
#define SMEM_BYTES (SMEM_FLOATS * 4)

typedef unsigned long long u64;

// column-softmaxed weights, o-major: g_wT[o*64 + i] = w[i][o]
__device__ float g_wT[64 * 64];

static __device__ __forceinline__ u64 ffma2(u64 a, u64 b, u64 c) {
    u64 d; asm("fma.rn.f32x2 %0,%1,%2,%3;" : "=l"(d) : "l"(a), "l"(b), "l"(c)); return d;
}
static __device__ __forceinline__ float hadd2(u64 v) {
    float lo, hi; asm("mov.b64 {%0,%1},%2;" : "=f"(lo), "=f"(hi) : "l"(v));
    return lo + hi;
}

// acos via A&S 4.4.45 7-term poly: abs err ~2e-8 on [-1,1]
static __device__ __forceinline__ float acos_fast(float x) {
    float ax = fabsf(x);
    float p = fmaf(ax, -0.0012624911f, 0.0066700901f);
    p = fmaf(p, ax, -0.0170881256f);
    p = fmaf(p, ax, 0.0308918810f);
    p = fmaf(p, ax, -0.0501743046f);
    p = fmaf(p, ax, 0.0889789874f);
    p = fmaf(p, ax, -0.2145988016f);
    p = fmaf(p, ax, 1.5707963050f);
    float om = 1.0f - ax;                       // >= 1e-7 after clipping
    float s = om * rsqrtf(fmaxf(om, 1e-30f));   // sqrt(1-ax)
    float r = p * s;
    return (x < 0.0f) ? 3.14159265358979f - r : r;
}

__global__ void wprep_kernel(const float* __restrict__ wraw) {
    int o = threadIdx.x;  // 64 threads, one output column each
    float s = 0.f;
    #pragma unroll 8
    for (int i = 0; i < 64; ++i) s += expf(wraw[i * 64 + o]);
    float inv = 1.0f / s;
    #pragma unroll 8
    for (int i = 0; i < 64; ++i) g_wT[o * 64 + i] = expf(wraw[i * 64 + o]) * inv;
}

__global__ __launch_bounds__(256, 3) void mfd_kernel(const float* __restrict__ xg,
                                                     float* __restrict__ out) {
    extern __shared__ float sm[];
    float* Xs  = sm;              // [64][PAD]  x rows (dd-contiguous)
    float* XT  = Xs + ARR;        // [64][PAD]  x transposed (i-contiguous per dd-row)
    float* As  = XT + ARR;        // [64][PAD]  current iterate a
    float* Fs  = As + ARR;        // [64][PAD]  F matrix (i-contiguous per o-row)
    float* Sxx = Fs + ARR;        // [64]  ||x_i||^2
    float* Saa = Sxx + 64;        // [64]  ||a_o||^2

    const int n   = blockIdx.x;
    const int tid = threadIdx.x;
    const int oc  = tid >> 4;     // 0..15  (warp = {2w, 2w+1} oc values)
    const int ic  = tid & 15;     // 0..15

    // ---- load x tile (coalesced float4) ----
    const float* xn = xg + (size_t)n * 4096;
    for (int t = tid; t < 1024; t += 256) {
        float4 v = ((const float4*)xn)[t];
        int r = t >> 4, c = (t & 15) << 2;
        *(float4*)&Xs[r * PAD + c] = v;
    }
    __syncthreads();

    // ---- transpose into XT, and per-row squared norms of x ----
    for (int t = tid; t < 1024; t += 256) {
        int dd = t >> 4, i0 = (t & 15) << 2;
        float4 v;
        v.x = Xs[(i0 + 0) * PAD + dd];
        v.y = Xs[(i0 + 1) * PAD + dd];
        v.z = Xs[(i0 + 2) * PAD + dd];
        v.w = Xs[(i0 + 3) * PAD + dd];
        *(float4*)&XT[dd * PAD + i0] = v;
    }
    if (tid < 64) {
        float s = 0.f;
        #pragma unroll
        for (int c = 0; c < 64; c += 4) {
            float4 v = *(float4*)&Xs[tid * PAD + c];
            s += v.x * v.x + v.y * v.y + v.z * v.z + v.w * v.w;
        }
        Sxx[tid] = s;
    }
    // ---- init a_o = x_0 for all o ----
    for (int t = tid; t < 1024; t += 256) {
        int r = t >> 4, c = (t & 15) << 2;
        *(float4*)&As[r * PAD + c] = *(float4*)&Xs[c];
    }
    __syncthreads();
    if (tid < 64) Saa[tid] = Sxx[0];
    __syncthreads();
    // From here on, every warp touches only its own Fs/As/Saa rows
    // (o = oc + 16k with oc in {2w, 2w+1}) -> warp-local sync suffices.

    const float HI = 1.0f - 1e-7f;

    #pragma unroll 1
    for (int it = 0; it < 3; ++it) {
        // ===== GEMM1 (f32x2 along dd): D[o][i] = sum_dd A[o][dd]*X[i][dd]
        u64 acc2[4][4];
        #pragma unroll
        for (int k = 0; k < 4; ++k)
            #pragma unroll
            for (int j = 0; j < 4; ++j) acc2[k][j] = 0ull;

        #pragma unroll 4
        for (int dd = 0; dd < 64; dd += 4) {
            ulonglong2 xp[4];
            #pragma unroll
            for (int j = 0; j < 4; ++j)
                xp[j] = *(const ulonglong2*)&Xs[(ic + 16 * j) * PAD + dd];
            #pragma unroll
            for (int k = 0; k < 4; ++k) {
                ulonglong2 ap = *(const ulonglong2*)&As[(oc + 16 * k) * PAD + dd];
                #pragma unroll
                for (int j = 0; j < 4; ++j) {
                    acc2[k][j] = ffma2(ap.x, xp[j].x, acc2[k][j]);
                    acc2[k][j] = ffma2(ap.y, xp[j].y, acc2[k][j]);
                }
            }
        }

        // ===== F[o][i] = w[i][o] * theta / ||v||, plus corr = sum_i F*dc
        float corr[4];
        #pragma unroll
        for (int k = 0; k < 4; ++k) {
            int o = oc + 16 * k;
            float sa = Saa[o];
            float cr = 0.f;
            #pragma unroll
            for (int j = 0; j < 4; ++j) {
                int i = ic + 16 * j;
                float draw  = hadd2(acc2[k][j]);
                float dc    = fminf(fmaxf(draw, -HI), HI);
                float theta = acos_fast(dc);
                float nv2   = Sxx[i] - dc * (2.0f * draw - dc * sa);
                float f     = (nv2 < 1e-14f) ? 1.0f : theta * rsqrtf(nv2);
                float F     = g_wT[o * 64 + i] * f;
                Fs[o * PAD + i] = F;
                cr = fmaf(F, dc, cr);
            }
            corr[k] = cr;
        }
        #pragma unroll
        for (int k = 0; k < 4; ++k) {
            #pragma unroll
            for (int s = 1; s < 16; s <<= 1)
                corr[k] += __shfl_xor_sync(0xffffffffu, corr[k], s);
        }
        __syncwarp();  // warp's Fs rows complete

        // ===== GEMM2 (f32x2 along i): G[o][dd] = sum_i F[o][i]*XT[dd][i]
        u64 g2[4][4];
        #pragma unroll
        for (int k = 0; k < 4; ++k)
            #pragma unroll
            for (int j = 0; j < 4; ++j) g2[k][j] = 0ull;

        #pragma unroll 4
        for (int i4 = 0; i4 < 64; i4 += 4) {
            ulonglong2 xtp[4];
            #pragma unroll
            for (int j = 0; j < 4; ++j)
                xtp[j] = *(const ulonglong2*)&XT[(ic + 16 * j) * PAD + i4];
            #pragma unroll
            for (int k = 0; k < 4; ++k) {
                ulonglong2 fp = *(const ulonglong2*)&Fs[(oc + 16 * k) * PAD + i4];
                #pragma unroll
                for (int j = 0; j < 4; ++j) {
                    g2[k][j] = ffma2(fp.x, xtp[j].x, g2[k][j]);
                    g2[k][j] = ffma2(fp.y, xtp[j].y, g2[k][j]);
                }
            }
        }

        // ===== exp-map update =====
        #pragma unroll
        for (int k = 0; k < 4; ++k) {
            int o = oc + 16 * k;
            float aold[4], grad[4];
            float gn2 = 0.f;
            #pragma unroll
            for (int j = 0; j < 4; ++j) {
                int dd = ic + 16 * j;
                aold[j] = As[o * PAD + dd];
                grad[j] = hadd2(g2[k][j]) - corr[k] * aold[j];
                gn2 = fmaf(grad[j], grad[j], gn2);
            }
            #pragma unroll
            for (int s = 1; s < 16; s <<= 1)
                gn2 += __shfl_xor_sync(0xffffffffu, gn2, s);
            float inv = rsqrtf(fmaxf(gn2, 1e-30f));
            float gn = gn2 * inv;                 // sqrt(gn2)
            float sg, cg;
            __sincosf(gn, &sg, &cg);
            float sc = (gn2 < 1e-14f) ? 1.0f : sg * inv;
            if (gn2 < 1e-14f) cg = 1.0f;

            if (it == 2) {
                #pragma unroll
                for (int j = 0; j < 4; ++j) {
                    int dd = ic + 16 * j;
                    out[(size_t)n * 4096 + o * 64 + dd] = fmaf(cg, aold[j], sc * grad[j]);
                }
            } else {
                float sa2 = 0.f;
                #pragma unroll
                for (int j = 0; j < 4; ++j) {
                    int dd = ic + 16 * j;
                    float an = fmaf(cg, aold[j], sc * grad[j]);
                    As[o * PAD + dd] = an;
                    sa2 = fmaf(an, an, sa2);
                }
                #pragma unroll
                for (int s = 1; s < 16; s <<= 1)
                    sa2 += __shfl_xor_sync(0xffffffffu, sa2, s);
                if (ic == 0) Saa[o] = sa2;
            }
        }
        __syncwarp();  // warp's As/Saa rows ready for its next iteration
    }
}

extern "C" void kernel_launch(void* const* d_in, const int* in_sizes, int n_in,
                              void* d_out, int out_size) {
    const float* x    = (const float*)d_in[0];   // (4,256,64,64)
    const float* wraw = (const float*)d_in[1];   // (64,64)
    float* out = (float*)d_out;                  // (4,256,64,64)

    cudaFuncSetAttribute(mfd_kernel, cudaFuncAttributeMaxDynamicSharedMemorySize, SMEM_BYTES);

    wprep_kernel<<<1, 64>>>(wraw);
    mfd_kernel<<<1024, 256, SMEM_BYTES>>>(x, out);
}

// round 6
// speedup vs baseline: 1.2847x; 1.0819x over previous
#include <cuda_runtime.h>
#include <math.h>

#define PAD 68
#define ARR (64 * PAD)
#define SMEM_FLOATS (3 * ARR + 128)
#define SMEM_BYTES (SMEM_FLOATS * 4)

typedef unsigned long long u64;

// column-softmaxed weights, o-major: g_wT[o*64 + i] = w[i][o]
__device__ float g_wT[64 * 64];

static __device__ __forceinline__ u64 ffma2(u64 a, u64 b, u64 c) {
    u64 d; asm("fma.rn.f32x2 %0,%1,%2,%3;" : "=l"(d) : "l"(a), "l"(b), "l"(c)); return d;
}
static __device__ __forceinline__ u64 fmul2(u64 a, u64 b) {
    u64 d; asm("mul.rn.f32x2 %0,%1,%2;" : "=l"(d) : "l"(a), "l"(b)); return d;
}
static __device__ __forceinline__ float hadd2(u64 v) {
    float lo, hi; asm("mov.b64 {%0,%1},%2;" : "=f"(lo), "=f"(hi) : "l"(v));
    return lo + hi;
}
static __device__ __forceinline__ void unpack2(u64 v, float& lo, float& hi) {
    asm("mov.b64 {%0,%1},%2;" : "=f"(lo), "=f"(hi) : "l"(v));
}
static __device__ __forceinline__ u64 bcast2(float f) {
    u64 d; asm("mov.b64 %0,{%1,%1};" : "=l"(d) : "f"(f)); return d;
}

// acos via A&S 4.4.45 7-term poly: abs err ~2e-8 on [-1,1]
static __device__ __forceinline__ float acos_fast(float x) {
    float ax = fabsf(x);
    float p = fmaf(ax, -0.0012624911f, 0.0066700901f);
    p = fmaf(p, ax, -0.0170881256f);
    p = fmaf(p, ax, 0.0308918810f);
    p = fmaf(p, ax, -0.0501743046f);
    p = fmaf(p, ax, 0.0889789874f);
    p = fmaf(p, ax, -0.2145988016f);
    p = fmaf(p, ax, 1.5707963050f);
    float om = 1.0f - ax;                       // >= 1e-7 after clipping
    float s = om * rsqrtf(fmaxf(om, 1e-30f));   // sqrt(1-ax)
    float r = p * s;
    return (x < 0.0f) ? 3.14159265358979f - r : r;
}

__global__ void wprep_kernel(const float* __restrict__ wraw) {
    int o = threadIdx.x;  // 64 threads, one output column each
    float s = 0.f;
    #pragma unroll 8
    for (int i = 0; i < 64; ++i) s += expf(wraw[i * 64 + o]);
    float inv = 1.0f / s;
    #pragma unroll 8
    for (int i = 0; i < 64; ++i) g_wT[o * 64 + i] = expf(wraw[i * 64 + o]) * inv;
}

__global__ __launch_bounds__(128, 4) void mfd_kernel(const float* __restrict__ xg,
                                                     float* __restrict__ out) {
    extern __shared__ float sm[];
    float* Xs  = sm;              // [64][PAD]  x rows (dd-contiguous)
    float* As  = Xs + ARR;        // [64][PAD]  current iterate a
    float* Fs  = As + ARR;        // [64][PAD]  F matrix (i-contiguous per o-row)
    float* Sxx = Fs + ARR;        // [64]  ||x_i||^2
    float* Saa = Sxx + 64;        // [64]  ||a_o||^2

    const int n   = blockIdx.x;
    const int tid = threadIdx.x;
    const int oc  = tid >> 4;     // 0..7  (warp = {2w, 2w+1} oc values)
    const int ic  = tid & 15;     // 0..15

    // ---- load x tile (coalesced float4) ----
    const float* xn = xg + (size_t)n * 4096;
    for (int t = tid; t < 1024; t += 128) {
        float4 v = ((const float4*)xn)[t];
        int r = t >> 4, c = (t & 15) << 2;
        *(float4*)&Xs[r * PAD + c] = v;
    }
    __syncthreads();

    // ---- per-row squared norms of x ----
    if (tid < 64) {
        float s = 0.f;
        #pragma unroll
        for (int c = 0; c < 64; c += 4) {
            float4 v = *(float4*)&Xs[tid * PAD + c];
            s += v.x * v.x + v.y * v.y + v.z * v.z + v.w * v.w;
        }
        Sxx[tid] = s;
    }
    // ---- init a_o = x_0 for all o ----
    for (int t = tid; t < 1024; t += 128) {
        int r = t >> 4, c = (t & 15) << 2;
        *(float4*)&As[r * PAD + c] = *(float4*)&Xs[c];
    }
    __syncthreads();
    if (tid < 64) Saa[tid] = Sxx[0];
    __syncthreads();
    // From here on each warp touches only its own As/Fs/Saa rows
    // (o = oc + 8k, oc in {2w,2w+1}) -> warp-local sync suffices.

    const float HI = 1.0f - 1e-7f;

    #pragma unroll 1
    for (int it = 0; it < 3; ++it) {
        // ===== GEMM1 (f32x2 along dd): D[o][i] = sum_dd A[o][dd]*X[i][dd]
        u64 acc2[8][4];
        #pragma unroll
        for (int k = 0; k < 8; ++k)
            #pragma unroll
            for (int j = 0; j < 4; ++j) acc2[k][j] = 0ull;

        #pragma unroll 4
        for (int dd = 0; dd < 64; dd += 4) {
            ulonglong2 xp[4];
            #pragma unroll
            for (int j = 0; j < 4; ++j)
                xp[j] = *(const ulonglong2*)&Xs[(ic + 16 * j) * PAD + dd];
            #pragma unroll
            for (int k = 0; k < 8; ++k) {
                ulonglong2 ap = *(const ulonglong2*)&As[(oc + 8 * k) * PAD + dd];
                #pragma unroll
                for (int j = 0; j < 4; ++j) {
                    acc2[k][j] = ffma2(ap.x, xp[j].x, acc2[k][j]);
                    acc2[k][j] = ffma2(ap.y, xp[j].y, acc2[k][j]);
                }
            }
        }

        // ===== F[o][i] = w[i][o] * theta / ||v||, plus corr = sum_i F*dc
        float sxx[4];
        #pragma unroll
        for (int j = 0; j < 4; ++j) sxx[j] = Sxx[ic + 16 * j];

        float corr[8];
        #pragma unroll
        for (int k = 0; k < 8; ++k) {
            int o = oc + 8 * k;
            float sa = Saa[o];
            float cr = 0.f;
            #pragma unroll
            for (int j = 0; j < 4; ++j) {
                int i = ic + 16 * j;
                float draw  = hadd2(acc2[k][j]);
                float dc    = fminf(fmaxf(draw, -HI), HI);
                float theta = acos_fast(dc);
                float nv2   = sxx[j] - dc * (2.0f * draw - dc * sa);
                float f     = (nv2 < 1e-14f) ? 1.0f : theta * rsqrtf(nv2);
                float F     = g_wT[o * 64 + i] * f;
                Fs[o * PAD + i] = F;
                cr = fmaf(F, dc, cr);
            }
            corr[k] = cr;
        }
        #pragma unroll
        for (int k = 0; k < 8; ++k) {
            #pragma unroll
            for (int s = 1; s < 16; s <<= 1)
                corr[k] += __shfl_xor_sync(0xffffffffu, corr[k], s);
        }
        __syncwarp();  // warp's Fs rows complete

        // ===== GEMM2 (f32x2 along dd-pairs, F broadcast):
        //       G[o][dd] = sum_i F[o][i] * X[i][dd]
        //       thread owns dd in {2ic, 2ic+1} (p=0) and {2ic+32, 2ic+33} (p=1)
        u64 g2[8][2];
        #pragma unroll
        for (int k = 0; k < 8; ++k) { g2[k][0] = 0ull; g2[k][1] = 0ull; }

        const int dlo = 2 * ic, dhi = 2 * ic + 32;
        #pragma unroll 4
        for (int i4 = 0; i4 < 64; i4 += 4) {
            u64 xl[4], xh[4];
            #pragma unroll
            for (int r = 0; r < 4; ++r) {
                xl[r] = *(const u64*)&Xs[(i4 + r) * PAD + dlo];
                xh[r] = *(const u64*)&Xs[(i4 + r) * PAD + dhi];
            }
            #pragma unroll
            for (int k = 0; k < 8; ++k) {
                ulonglong2 fp = *(const ulonglong2*)&Fs[(oc + 8 * k) * PAD + i4];
                float f0, f1, f2, f3;
                unpack2(fp.x, f0, f1);
                unpack2(fp.y, f2, f3);
                u64 b0 = bcast2(f0), b1 = bcast2(f1), b2 = bcast2(f2), b3 = bcast2(f3);
                g2[k][0] = ffma2(b0, xl[0], g2[k][0]);
                g2[k][0] = ffma2(b1, xl[1], g2[k][0]);
                g2[k][0] = ffma2(b2, xl[2], g2[k][0]);
                g2[k][0] = ffma2(b3, xl[3], g2[k][0]);
                g2[k][1] = ffma2(b0, xh[0], g2[k][1]);
                g2[k][1] = ffma2(b1, xh[1], g2[k][1]);
                g2[k][1] = ffma2(b2, xh[2], g2[k][1]);
                g2[k][1] = ffma2(b3, xh[3], g2[k][1]);
            }
        }

        // ===== exp-map update (f32x2 on dd pairs) =====
        #pragma unroll
        for (int k = 0; k < 8; ++k) {
            int o = oc + 8 * k;
            u64 a0 = *(const u64*)&As[o * PAD + dlo];
            u64 a1 = *(const u64*)&As[o * PAD + dhi];
            u64 ncb = bcast2(-corr[k]);
            u64 gr0 = ffma2(ncb, a0, g2[k][0]);
            u64 gr1 = ffma2(ncb, a1, g2[k][1]);
            float q0, q1, q2, q3;
            unpack2(gr0, q0, q1);
            unpack2(gr1, q2, q3);
            float gn2 = q0 * q0;
            gn2 = fmaf(q1, q1, gn2);
            gn2 = fmaf(q2, q2, gn2);
            gn2 = fmaf(q3, q3, gn2);
            #pragma unroll
            for (int s = 1; s < 16; s <<= 1)
                gn2 += __shfl_xor_sync(0xffffffffu, gn2, s);
            float inv = rsqrtf(fmaxf(gn2, 1e-30f));
            float gn = gn2 * inv;                 // sqrt(gn2)
            float sg, cg;
            __sincosf(gn, &sg, &cg);
            float sc = (gn2 < 1e-14f) ? 1.0f : sg * inv;
            if (gn2 < 1e-14f) cg = 1.0f;

            u64 cgb = bcast2(cg), scb = bcast2(sc);
            u64 an0 = ffma2(cgb, a0, fmul2(scb, gr0));
            u64 an1 = ffma2(cgb, a1, fmul2(scb, gr1));

            if (it == 2) {
                *(u64*)&out[(size_t)n * 4096 + o * 64 + dlo] = an0;
                *(u64*)&out[(size_t)n * 4096 + o * 64 + dhi] = an1;
            } else {
                *(u64*)&As[o * PAD + dlo] = an0;
                *(u64*)&As[o * PAD + dhi] = an1;
                float p0, p1, p2, p3;
                unpack2(an0, p0, p1);
                unpack2(an1, p2, p3);
                float sa2 = p0 * p0;
                sa2 = fmaf(p1, p1, sa2);
                sa2 = fmaf(p2, p2, sa2);
                sa2 = fmaf(p3, p3, sa2);
                #pragma unroll
                for (int s = 1; s < 16; s <<= 1)
                    sa2 += __shfl_xor_sync(0xffffffffu, sa2, s);
                if (ic == 0) Saa[o] = sa2;
            }
        }
        __syncwarp();  // warp's As/Saa rows ready for its next iteration
    }
}

extern "C" void kernel_launch(void* const* d_in, const int* in_sizes, int n_in,
                              void* d_out, int out_size) {
    const float* x    = (const float*)d_in[0];   // (4,256,64,64)
    const float* wraw = (const float*)d_in[1];   // (64,64)
    float* out = (float*)d_out;                  // (4,256,64,64)

    cudaFuncSetAttribute(mfd_kernel, cudaFuncAttributeMaxDynamicSharedMemorySize, SMEM_BYTES);

    wprep_kernel<<<1, 64>>>(wraw);
    mfd_kernel<<<1024, 128, SMEM_BYTES>>>(x, out);
}

// round 9
// speedup vs baseline: 1.4299x; 1.1130x over previous
#include <cuda_runtime.h>
#include <math.h>

#define PAD 68
#define ARR (64 * PAD)
#define SMEM_FLOATS (3 * ARR + 32)
#define SMEM_BYTES (SMEM_FLOATS * 4)

typedef unsigned long long u64;

// column-softmaxed weights, o-major: g_wT[o*64 + i] = w[i][o]
__device__ float g_wT[64 * 64];

static __device__ __forceinline__ u64 ffma2(u64 a, u64 b, u64 c) {
    u64 d; asm("fma.rn.f32x2 %0,%1,%2,%3;" : "=l"(d) : "l"(a), "l"(b), "l"(c)); return d;
}
static __device__ __forceinline__ u64 fmul2(u64 a, u64 b) {
    u64 d; asm("mul.rn.f32x2 %0,%1,%2;" : "=l"(d) : "l"(a), "l"(b)); return d;
}
static __device__ __forceinline__ float hadd2(u64 v) {
    float lo, hi; asm("mov.b64 {%0,%1},%2;" : "=f"(lo), "=f"(hi) : "l"(v));
    return lo + hi;
}
static __device__ __forceinline__ void unpack2(u64 v, float& lo, float& hi) {
    asm("mov.b64 {%0,%1},%2;" : "=f"(lo), "=f"(hi) : "l"(v));
}
static __device__ __forceinline__ u64 bcast2(float f) {
    u64 d; asm("mov.b64 %0,{%1,%1};" : "=l"(d) : "f"(f)); return d;
}

// acos via A&S 4.4.45 7-term poly, Estrin form (depth ~4): abs err ~2e-8
static __device__ __forceinline__ float acos_fast(float x) {
    float ax = fabsf(x);
    float om = 1.0f - ax;                       // >= 1e-7 after clipping
    float s = om * rsqrtf(fmaxf(om, 1e-30f));   // sqrt(1-ax), MUFU issued early
    float x2 = ax * ax;
    float x4 = x2 * x2;
    float p01 = fmaf(ax, -0.2145988016f, 1.5707963050f);
    float p23 = fmaf(ax, -0.0501743046f, 0.0889789874f);
    float p45 = fmaf(ax, -0.0170881256f, 0.0308918810f);
    float p67 = fmaf(ax, -0.0012624911f, 0.0066700901f);
    float q0 = fmaf(p23, x2, p01);
    float q1 = fmaf(p67, x2, p45);
    float p = fmaf(q1, x4, q0);
    float r = p * s;
    return (x < 0.0f) ? 3.14159265358979f - r : r;
}

__global__ void wprep_kernel(const float* __restrict__ wraw) {
    int o = threadIdx.x;  // 64 threads, one output column each
    float s = 0.f;
    #pragma unroll 8
    for (int i = 0; i < 64; ++i) s += expf(wraw[i * 64 + o]);
    float inv = 1.0f / s;
    #pragma unroll 8
    for (int i = 0; i < 64; ++i) g_wT[o * 64 + i] = expf(wraw[i * 64 + o]) * inv;
}

__global__ __launch_bounds__(128, 4) void mfd_kernel(const float* __restrict__ xg,
                                                     float* __restrict__ out) {
    extern __shared__ float sm[];
    float* Xs  = sm;              // [64][PAD]  x rows (dd-contiguous)
    float* As  = Xs + ARR;        // [64][PAD]  current iterate a
    float* Fs  = As + ARR;        // [64][PAD]  F matrix (i-contiguous per o-row)

    const int n   = blockIdx.x;
    const int tid = threadIdx.x;
    const int oc  = tid >> 4;     // 0..7  (warp = {2w, 2w+1} oc values)
    const int ic  = tid & 15;     // 0..15

    // ---- load x tile (coalesced float4) ----
    const float* xn = xg + (size_t)n * 4096;
    for (int t = tid; t < 1024; t += 128) {
        float4 v = ((const float4*)xn)[t];
        int r = t >> 4, c = (t & 15) << 2;
        *(float4*)&Xs[r * PAD + c] = v;
    }
    __syncthreads();

    // ---- init a_o = x_0 for all o ----
    for (int t = tid; t < 1024; t += 128) {
        int r = t >> 4, c = (t & 15) << 2;
        *(float4*)&As[r * PAD + c] = *(float4*)&Xs[c];
    }
    __syncthreads();
    // Inputs are unit vectors and the exp-map preserves unit norm to rounding,
    // so ||v||^2 = 1 - dc^2 (robust, branch-free; see acos clipping note).
    // From here on each warp touches only its own As/Fs rows
    // (o = oc + 8k, oc in {2w,2w+1}) -> warp-local sync suffices.

    const float HI = 1.0f - 1e-7f;

    #pragma unroll 1
    for (int it = 0; it < 3; ++it) {
        // ===== GEMM1 (f32x2 along dd): D[o][i] = sum_dd A[o][dd]*X[i][dd]
        u64 acc2[8][4];
        #pragma unroll
        for (int k = 0; k < 8; ++k)
            #pragma unroll
            for (int j = 0; j < 4; ++j) acc2[k][j] = 0ull;

        #pragma unroll 4
        for (int dd = 0; dd < 64; dd += 4) {
            ulonglong2 xp[4];
            #pragma unroll
            for (int j = 0; j < 4; ++j)
                xp[j] = *(const ulonglong2*)&Xs[(ic + 16 * j) * PAD + dd];
            #pragma unroll
            for (int k = 0; k < 8; ++k) {
                ulonglong2 ap = *(const ulonglong2*)&As[(oc + 8 * k) * PAD + dd];
                #pragma unroll
                for (int j = 0; j < 4; ++j) {
                    acc2[k][j] = ffma2(ap.x, xp[j].x, acc2[k][j]);
                    acc2[k][j] = ffma2(ap.y, xp[j].y, acc2[k][j]);
                }
            }
        }

        // ===== F[o][i] = w[i][o] * theta / ||v||, partial corr = sum_i F*dc
        float corr[8];
        #pragma unroll
        for (int k = 0; k < 8; ++k) {
            int o = oc + 8 * k;
            float cr = 0.f;
            #pragma unroll
            for (int j = 0; j < 4; ++j) {
                int i = ic + 16 * j;
                float draw  = hadd2(acc2[k][j]);
                float dc    = fminf(fmaxf(draw, -HI), HI);
                float theta = acos_fast(dc);
                // ||v||^2 = 1 - dc^2  (exact when unclipped; >= 2e-7 always)
                float nv2   = fmaf(-dc, dc, 1.0f);
                float f     = theta * rsqrtf(nv2);
                float F     = g_wT[o * 64 + i] * f;
                Fs[o * PAD + i] = F;
                cr = fmaf(F, dc, cr);
            }
            corr[k] = cr;
        }
        __syncwarp();  // warp's Fs rows complete

        // ===== GEMM2 (f32x2 along dd-pairs, F broadcast):
        //       G[o][dd] = sum_i F[o][i] * X[i][dd]
        //       thread owns dd in {2ic, 2ic+1} and {2ic+32, 2ic+33}
        u64 g2[8][2];
        #pragma unroll
        for (int k = 0; k < 8; ++k) { g2[k][0] = 0ull; g2[k][1] = 0ull; }

        const int dlo = 2 * ic, dhi = 2 * ic + 32;
        #pragma unroll 4
        for (int i4 = 0; i4 < 64; i4 += 4) {
            u64 xl[4], xh[4];
            #pragma unroll
            for (int r = 0; r < 4; ++r) {
                xl[r] = *(const u64*)&Xs[(i4 + r) * PAD + dlo];
                xh[r] = *(const u64*)&Xs[(i4 + r) * PAD + dhi];
            }
            #pragma unroll
            for (int k = 0; k < 8; ++k) {
                ulonglong2 fp = *(const ulonglong2*)&Fs[(oc + 8 * k) * PAD + i4];
                float f0, f1, f2, f3;
                unpack2(fp.x, f0, f1);
                unpack2(fp.y, f2, f3);
                u64 b0 = bcast2(f0), b1 = bcast2(f1), b2 = bcast2(f2), b3 = bcast2(f3);
                g2[k][0] = ffma2(b0, xl[0], g2[k][0]);
                g2[k][0] = ffma2(b1, xl[1], g2[k][0]);
                g2[k][0] = ffma2(b2, xl[2], g2[k][0]);
                g2[k][0] = ffma2(b3, xl[3], g2[k][0]);
                g2[k][1] = ffma2(b0, xh[0], g2[k][1]);
                g2[k][1] = ffma2(b1, xh[1], g2[k][1]);
                g2[k][1] = ffma2(b2, xh[2], g2[k][1]);
                g2[k][1] = ffma2(b3, xh[3], g2[k][1]);
            }
        }

        // corr reduction deferred here: SHFL latency overlapped GEMM2 issue
        #pragma unroll
        for (int k = 0; k < 8; ++k) {
            #pragma unroll
            for (int s = 1; s < 16; s <<= 1)
                corr[k] += __shfl_xor_sync(0xffffffffu, corr[k], s);
        }

        // ===== exp-map update (f32x2 on dd pairs) =====
        #pragma unroll
        for (int k = 0; k < 8; ++k) {
            int o = oc + 8 * k;
            u64 a0 = *(const u64*)&As[o * PAD + dlo];
            u64 a1 = *(const u64*)&As[o * PAD + dhi];
            u64 ncb = bcast2(-corr[k]);
            u64 gr0 = ffma2(ncb, a0, g2[k][0]);
            u64 gr1 = ffma2(ncb, a1, g2[k][1]);
            float q0, q1, q2, q3;
            unpack2(gr0, q0, q1);
            unpack2(gr1, q2, q3);
            float gn2 = q0 * q0;
            gn2 = fmaf(q1, q1, gn2);
            gn2 = fmaf(q2, q2, gn2);
            gn2 = fmaf(q3, q3, gn2);
            #pragma unroll
            for (int s = 1; s < 16; s <<= 1)
                gn2 += __shfl_xor_sync(0xffffffffu, gn2, s);
            float inv = rsqrtf(fmaxf(gn2, 1e-30f));
            float gn = gn2 * inv;                 // sqrt(gn2)
            float sg, cg;
            __sincosf(gn, &sg, &cg);
            float sc = (gn2 < 1e-14f) ? 1.0f : sg * inv;
            if (gn2 < 1e-14f) cg = 1.0f;

            u64 cgb = bcast2(cg), scb = bcast2(sc);
            u64 an0 = ffma2(cgb, a0, fmul2(scb, gr0));
            u64 an1 = ffma2(cgb, a1, fmul2(scb, gr1));

            if (it == 2) {
                *(u64*)&out[(size_t)n * 4096 + o * 64 + dlo] = an0;
                *(u64*)&out[(size_t)n * 4096 + o * 64 + dhi] = an1;
            } else {
                *(u64*)&As[o * PAD + dlo] = an0;
                *(u64*)&As[o * PAD + dhi] = an1;
            }
        }
        __syncwarp();  // warp's As rows ready for its next iteration
    }
}

extern "C" void kernel_launch(void* const* d_in, const int* in_sizes, int n_in,
                              void* d_out, int out_size) {
    const float* x    = (const float*)d_in[0];   // (4,256,64,64)
    const float* wraw = (const float*)d_in[1];   // (64,64)
    float* out = (float*)d_out;                  // (4,256,64,64)

    cudaFuncSetAttribute(mfd_kernel, cudaFuncAttributeMaxDynamicSharedMemorySize, SMEM_BYTES);

    wprep_kernel<<<1, 64>>>(wraw);
    mfd_kernel<<<1024, 128, SMEM_BYTES>>>(x, out);
}